// round 14
// baseline (speedup 1.0000x reference)
#include <cuda_runtime.h>
#include <cuda_bf16.h>
#include <math.h>
#include <stdint.h>

// ---------------- scratch (__device__ globals: no allocation allowed) --------
__device__ float g_qc0[800];
__device__ float g_M[33 * 800];
__device__ float g_weff[32 * 800];
__device__ float g_cst[64];
__device__ float g_part[32 * 6 * 3 * 1024];
__device__ int   g_counter;

// bf16-split operands
__device__ __nv_bfloat16 g_xhi[32 * 1024 * 1024];  // x transposed: [b][m][c]
__device__ __nv_bfloat16 g_xlo[32 * 1024 * 1024];
__device__ __nv_bfloat16 g_whi[768 * 1024];        // [e][c]
__device__ __nv_bfloat16 g_wlo[768 * 1024];

// ---------------- helpers ----------------------------------------------------
__device__ __forceinline__ uint32_t smem_u32(const void* p) {
    uint32_t a;
    asm("{ .reg .u64 t; cvta.to.shared.u64 t, %1; cvt.u32.u64 %0, t; }"
        : "=r"(a) : "l"(p));
    return a;
}
__device__ __forceinline__ void cp16(uint32_t dst, const void* src) {
    asm volatile("cp.async.cg.shared.global [%0], [%1], 16;"
                 :: "r"(dst), "l"(src) : "memory");
}
#define CP_COMMIT() asm volatile("cp.async.commit_group;" ::: "memory")
#define CP_WAIT(N)  asm volatile("cp.async.wait_group %0;" :: "n"(N) : "memory")

__device__ __forceinline__ void ldsm4(uint32_t* r, uint32_t addr) {
    asm volatile("ldmatrix.sync.aligned.m8n8.x4.shared.b16 {%0,%1,%2,%3}, [%4];"
                 : "=r"(r[0]), "=r"(r[1]), "=r"(r[2]), "=r"(r[3]) : "r"(addr));
}
__device__ __forceinline__ void mma16816(float* d, const uint32_t* a,
                                         uint32_t b0, uint32_t b1) {
    asm volatile(
        "mma.sync.aligned.m16n8k16.row.col.f32.bf16.bf16.f32 "
        "{%0,%1,%2,%3}, {%4,%5,%6,%7}, {%8,%9}, {%0,%1,%2,%3};"
        : "+f"(d[0]), "+f"(d[1]), "+f"(d[2]), "+f"(d[3])
        : "r"(a[0]), "r"(a[1]), "r"(a[2]), "r"(a[3]), "r"(b0), "r"(b1));
}

// ============================================================================
// prepA1: qc0[d] = bq[d] + Wq[d,:768].cls + zero g_M + reset counter
// ============================================================================
__global__ void prepA1(const float* __restrict__ cls,
                       const float* __restrict__ qkv_w,
                       const float* __restrict__ qkv_b)
{
    const int tid = threadIdx.x;
    const int gtid = blockIdx.x * 256 + tid;
    for (int f = gtid; f < 33 * 800; f += 100 * 256) g_M[f] = 0.f;
    if (gtid == 0) g_counter = 0;

    const int d = blockIdx.x * 8 + (tid >> 5);
    const int lane = tid & 31;
    const float* wr = qkv_w + (size_t)d * 800;
    float acc = 0.f;
    for (int e = lane; e < 768; e += 32) acc = fmaf(wr[e], cls[e], acc);
    #pragma unroll
    for (int off = 16; off; off >>= 1)
        acc += __shfl_xor_sync(0xffffffffu, acc, off);
    if (lane == 0) g_qc0[d] = acc + qkv_b[d];
}

// ============================================================================
// prepA2: g_M[i][e] += sum_d u[d][i] * Wk[d][e]   (d split into 32 chunks)
// ============================================================================
#define DCH 25
__global__ void prepA2(const float* __restrict__ qkv_w)
{
    __shared__ __align__(16) float us[DCH * 36];
    const int tid = threadIdx.x;
    const int e = blockIdx.x * 128 + tid;
    const int d0 = blockIdx.y * DCH;

    for (int f = tid; f < DCH * 36; f += 128) {
        int dd = f / 36, i = f - dd * 36;
        float v = 0.f;
        if (i == 0)       v = g_qc0[d0 + dd];
        else if (i < 33)  v = qkv_w[(size_t)(d0 + dd) * 800 + 768 + (i - 1)];
        us[f] = v;
    }
    __syncthreads();
    if (e >= 800) return;

    float4 a[9];
    #pragma unroll
    for (int q = 0; q < 9; q++) a[q] = make_float4(0.f, 0.f, 0.f, 0.f);

    const float* wkp = qkv_w + (size_t)(800 + d0) * 800 + e;
    #pragma unroll
    for (int dd = 0; dd < DCH; dd++) {
        float wk = wkp[(size_t)dd * 800];
        const float4* up = (const float4*)&us[dd * 36];
        #pragma unroll
        for (int q = 0; q < 9; q++) {
            float4 u = up[q];
            a[q].x = fmaf(u.x, wk, a[q].x);
            a[q].y = fmaf(u.y, wk, a[q].y);
            a[q].z = fmaf(u.z, wk, a[q].z);
            a[q].w = fmaf(u.w, wk, a[q].w);
        }
    }
    #pragma unroll
    for (int q = 0; q < 9; q++) {
        float c[4] = {a[q].x, a[q].y, a[q].z, a[q].w};
        #pragma unroll
        for (int k = 0; k < 4; k++) {
            int i = q * 4 + k;
            if (i < 33) atomicAdd(&g_M[i * 800 + e], c[k]);
        }
    }
}

// ============================================================================
// prepB: per batch — w_eff = M[0] + g@M[1:], S1, K2
// ============================================================================
__global__ void prepB(const float* __restrict__ gender,
                      const float* __restrict__ qkv_w,
                      const float* __restrict__ qkv_b,
                      const float* __restrict__ ln_g,
                      const float* __restrict__ ln_b)
{
    __shared__ float gs[32];
    __shared__ float red[24];
    const int b = blockIdx.x, tid = threadIdx.x;
    if (tid < 32) gs[tid] = gender[b * 32 + tid];
    __syncthreads();

    float ps1 = 0.f, ps2 = 0.f, pex = 0.f;
    for (int e = tid; e < 800; e += 256) {
        float wf = g_M[e];
        #pragma unroll
        for (int j = 0; j < 32; j++) wf = fmaf(gs[j], g_M[(1 + j) * 800 + e], wf);
        g_weff[b * 800 + e] = wf;
        if (e < 768) { ps1 = fmaf(ln_g[e], wf, ps1); ps2 = fmaf(ln_b[e], wf, ps2); }
        else         { pex = fmaf(gs[e - 768], wf, pex); }
    }
    for (int d = tid; d < 800; d += 256) {
        float qd = g_qc0[d];
        const float* wq = qkv_w + (size_t)d * 800 + 768;
        #pragma unroll
        for (int j = 0; j < 32; j++) qd = fmaf(wq[j], gs[j], qd);
        pex = fmaf(qd, qkv_b[800 + d], pex);
    }
    #pragma unroll
    for (int off = 16; off; off >>= 1) {
        ps1 += __shfl_xor_sync(0xffffffffu, ps1, off);
        ps2 += __shfl_xor_sync(0xffffffffu, ps2, off);
        pex += __shfl_xor_sync(0xffffffffu, pex, off);
    }
    const int w = tid >> 5;
    if ((tid & 31) == 0) { red[w] = ps1; red[8 + w] = ps2; red[16 + w] = pex; }
    __syncthreads();
    if (tid == 0) {
        float S1 = 0.f, S2 = 0.f, EX = 0.f;
        for (int i = 0; i < 8; i++) { S1 += red[i]; S2 += red[8 + i]; EX += red[16 + i]; }
        g_cst[b * 2 + 0] = S1;
        g_cst[b * 2 + 1] = S2 + EX;
    }
}

// ============================================================================
// conv_w: split conv weights into bf16 hi/lo. 768 blocks x 256.
// ============================================================================
__global__ void conv_w_kernel(const float* __restrict__ W)
{
    int i = blockIdx.x * 256 + threadIdx.x;
    #pragma unroll
    for (int k = 0; k < 4; k++) {
        int idx = i + k * 196608;
        float v = W[idx];
        __nv_bfloat16 h = __float2bfloat16(v);
        float r = v - __bfloat162float(h);
        g_whi[idx] = h;
        g_wlo[idx] = __float2bfloat16(r);
    }
}

// ============================================================================
// conv_x: transpose x[b][c][m] -> x_t[b][m][c], split into bf16 hi/lo,
// coalesced __nv_bfloat162 writes. 64c x 32m tiles.
// ============================================================================
__global__ void conv_x_kernel(const float* __restrict__ x)
{
    __shared__ float s[32][66];
    const int b = blockIdx.z;
    const int m0 = blockIdx.x * 32;
    const int c0 = blockIdx.y * 64;
    const int tid = threadIdx.x;

    const float* xp = x + ((size_t)b * 1024 + c0) * 1024 + m0;
    #pragma unroll
    for (int i = 0; i < 8; i++) {
        int idx = tid + i * 256;
        int cl = idx >> 5, ml = idx & 31;
        s[ml][cl] = xp[(size_t)cl * 1024 + ml];
    }
    __syncthreads();

    const size_t ob = ((size_t)b * 1024 + m0) * 1024 + c0;
    #pragma unroll
    for (int i = 0; i < 4; i++) {
        int idx = tid + i * 256;
        int ml = idx >> 5, pc = idx & 31;
        float2 v = *(const float2*)&s[ml][2 * pc];
        __nv_bfloat16 h0 = __float2bfloat16(v.x);
        __nv_bfloat16 h1 = __float2bfloat16(v.y);
        __nv_bfloat16 l0 = __float2bfloat16(v.x - __bfloat162float(h0));
        __nv_bfloat16 l1 = __float2bfloat16(v.y - __bfloat162float(h1));
        __nv_bfloat162 hp; hp.x = h0; hp.y = h1;
        __nv_bfloat162 lp; lp.x = l0; lp.y = l1;
        *(__nv_bfloat162*)&g_xhi[ob + (size_t)ml * 1024 + 2 * pc] = hp;
        *(__nv_bfloat162*)&g_xlo[ob + (size_t)ml * 1024 + 2 * pc] = lp;
    }
}

// ============================================================================
// fused_mma: persistent mma.sync bf16 GEMM + LN-stat fold.  N=256 tasks.
// Task = (b, m-tile 128, ep3 of 256 e). 768 tasks. 512 threads (4m x 4n warps,
// warp tile 32x64). K-chunk 32, cp.async 3-stage / depth-2 pipeline:
//   CP_WAIT(1) -> sync -> issue(kc+2) into buf (kc+2)%3 -> compute(kc).
// Per-chunk regions (80B padded rows): Ah[128] Al[128] Bh[256] Bl[256].
// ============================================================================
#define BUFB 61440               // 768 rows * 80 bytes
#define TILES_BYTES (3 * BUFB)   // 184320
#define OFF_AL 10240
#define OFF_BH 20480
#define OFF_BL 40960

__global__ __launch_bounds__(512, 1)
void fused_mma(const float* __restrict__ conv_b, const float* __restrict__ ln_g)
{
    extern __shared__ __align__(16) char tiles[];
    __shared__ float uS[256];
    __shared__ float cbS[256];
    __shared__ float redS[3 * 3 * 128];   // [wn-1][q][m]
    __shared__ int s_task;

    const uint32_t ts = smem_u32(tiles);
    const int tid = threadIdx.x;
    const int wid = tid >> 5, lane = tid & 31;
    const int wm = wid & 3, wn = wid >> 2;

    const int r0 = tid >> 2, part0 = tid & 3;

    const uint32_t aoff = (uint32_t)((wm * 32 + (lane & 15)) * 80 + (lane >> 4) * 16);
    const int bg = lane >> 3, br = lane & 7;
    const uint32_t boff = (uint32_t)((wn * 64 + ((bg >= 2) ? 8 : 0) + br) * 80 + (bg & 1) * 16);

    while (true) {
        if (tid == 0) s_task = atomicAdd(&g_counter, 1);
        __syncthreads();
        const int task = s_task;
        if (task >= 768) return;

        const int b  = task / 24;
        const int r_ = task - b * 24;
        const int mt_ = r_ / 3;
        const int ep3 = r_ - mt_ * 3;
        const int m0 = mt_ * 128;
        const int E0 = ep3 * 256;

        if (tid < 256) {
            uS[tid]  = ln_g[E0 + tid] * g_weff[b * 800 + E0 + tid];
            cbS[tid] = conv_b[E0 + tid];
        }

        const __nv_bfloat16* srcA_h = g_xhi + (size_t)b * 1048576 + (size_t)m0 * 1024;
        const __nv_bfloat16* srcA_l = g_xlo + (size_t)b * 1048576 + (size_t)m0 * 1024;
        const __nv_bfloat16* srcB_h = g_whi + (size_t)E0 * 1024;
        const __nv_bfloat16* srcB_l = g_wlo + (size_t)E0 * 1024;

        // one chunk = 6 cp16 per thread; each unrolled p covers one region
        auto issue = [&](int c, int buf) {
            const int c0 = c * 32 + part0 * 8;
            const uint32_t base = ts + (uint32_t)buf * BUFB + (uint32_t)(r0 * 80 + part0 * 16);
            cp16(base,                            srcA_h + (size_t)r0 * 1024 + c0);
            cp16(base + OFF_AL,                   srcA_l + (size_t)r0 * 1024 + c0);
            cp16(base + OFF_BH,                   srcB_h + (size_t)r0 * 1024 + c0);
            cp16(base + OFF_BH + 128 * 80,        srcB_h + (size_t)(r0 + 128) * 1024 + c0);
            cp16(base + OFF_BL,                   srcB_l + (size_t)r0 * 1024 + c0);
            cp16(base + OFF_BL + 128 * 80,        srcB_l + (size_t)(r0 + 128) * 1024 + c0);
            CP_COMMIT();
        };

        issue(0, 0);
        issue(1, 1);

        float acc[2][8][4];
        #pragma unroll
        for (int i = 0; i < 2; i++)
            #pragma unroll
            for (int j = 0; j < 8; j++)
                #pragma unroll
                for (int k = 0; k < 4; k++) acc[i][j][k] = 0.f;

        for (int kc = 0; kc < 32; kc++) {
            CP_WAIT(1);
            __syncthreads();
            if (kc < 30) issue(kc + 2, (kc + 2) % 3);

            const uint32_t base = ts + (uint32_t)(kc % 3) * BUFB;
            const uint32_t tAh = base, tAl = base + OFF_AL;
            const uint32_t tBh = base + OFF_BH, tBl = base + OFF_BL;

            #pragma unroll
            for (int ks = 0; ks < 2; ks++) {
                const uint32_t ko = ks * 32;
                uint32_t ah[2][4], al[2][4], bb[4][4];
                #pragma unroll
                for (int mt = 0; mt < 2; mt++) {
                    ldsm4(ah[mt], tAh + aoff + mt * 1280 + ko);
                    ldsm4(al[mt], tAl + aoff + mt * 1280 + ko);
                }
                // B hi: hh + lh
                #pragma unroll
                for (int p = 0; p < 4; p++)
                    ldsm4(bb[p], tBh + boff + p * 1280 + ko);
                #pragma unroll
                for (int mt = 0; mt < 2; mt++)
                    #pragma unroll
                    for (int nt = 0; nt < 8; nt++) {
                        const int p = nt >> 1, o = (nt & 1) * 2;
                        mma16816(acc[mt][nt], ah[mt], bb[p][o], bb[p][o + 1]);
                        mma16816(acc[mt][nt], al[mt], bb[p][o], bb[p][o + 1]);
                    }
                // B lo: hl
                #pragma unroll
                for (int p = 0; p < 4; p++)
                    ldsm4(bb[p], tBl + boff + p * 1280 + ko);
                #pragma unroll
                for (int mt = 0; mt < 2; mt++)
                    #pragma unroll
                    for (int nt = 0; nt < 8; nt++) {
                        const int p = nt >> 1, o = (nt & 1) * 2;
                        mma16816(acc[mt][nt], ah[mt], bb[p][o], bb[p][o + 1]);
                    }
            }
        }

        // ---- epilogue: fold acc into (s1, s2, sd) ----
        float rs[2][2][3];
        #pragma unroll
        for (int mt = 0; mt < 2; mt++)
            #pragma unroll
            for (int h = 0; h < 2; h++) {
                float s1 = 0.f, s2 = 0.f, sd = 0.f;
                #pragma unroll
                for (int nt = 0; nt < 8; nt++) {
                    #pragma unroll
                    for (int j = 0; j < 2; j++) {
                        const int eL = wn * 64 + nt * 8 + (lane & 3) * 2 + j;
                        float p = acc[mt][nt][h * 2 + j] + cbS[eL];
                        s1 += p;
                        s2 = fmaf(p, p, s2);
                        sd = fmaf(p, uS[eL], sd);
                    }
                }
                rs[mt][h][0] = s1; rs[mt][h][1] = s2; rs[mt][h][2] = sd;
            }
        #pragma unroll
        for (int mt = 0; mt < 2; mt++)
            #pragma unroll
            for (int h = 0; h < 2; h++)
                #pragma unroll
                for (int q = 0; q < 3; q++) {
                    rs[mt][h][q] += __shfl_xor_sync(0xffffffffu, rs[mt][h][q], 1);
                    rs[mt][h][q] += __shfl_xor_sync(0xffffffffu, rs[mt][h][q], 2);
                }

        __syncthreads();
        if (wn > 0 && (lane & 3) == 0) {
            #pragma unroll
            for (int mt = 0; mt < 2; mt++)
                #pragma unroll
                for (int h = 0; h < 2; h++) {
                    const int m = wm * 32 + mt * 16 + h * 8 + (lane >> 2);
                    redS[((wn - 1) * 3 + 0) * 128 + m] = rs[mt][h][0];
                    redS[((wn - 1) * 3 + 1) * 128 + m] = rs[mt][h][1];
                    redS[((wn - 1) * 3 + 2) * 128 + m] = rs[mt][h][2];
                }
        }
        __syncthreads();
        if (wn == 0 && (lane & 3) == 0) {
            const int basep = ((b * 3 + ep3) * 3) * 1024 + m0;
            #pragma unroll
            for (int mt = 0; mt < 2; mt++)
                #pragma unroll
                for (int h = 0; h < 2; h++) {
                    const int m = wm * 32 + mt * 16 + h * 8 + (lane >> 2);
                    float s1 = rs[mt][h][0], s2 = rs[mt][h][1], sd = rs[mt][h][2];
                    #pragma unroll
                    for (int w2 = 0; w2 < 3; w2++) {
                        s1 += redS[(w2 * 3 + 0) * 128 + m];
                        s2 += redS[(w2 * 3 + 1) * 128 + m];
                        sd += redS[(w2 * 3 + 2) * 128 + m];
                    }
                    g_part[basep + m]        = s1;
                    g_part[basep + 1024 + m] = s2;
                    g_part[basep + 2048 + m] = sd;
                }
        }
    }
}

// ============================================================================
// final: combine 3 e-pass partials -> score -> softmax -> out (B,1,32,32)
// ============================================================================
__global__ void final_kernel(float* __restrict__ out)
{
    __shared__ float sc[1024];
    __shared__ float red[8];
    const int b = blockIdx.x, tid = threadIdx.x;
    const float S1 = g_cst[b * 2 + 0];
    const float K2 = g_cst[b * 2 + 1];

    #pragma unroll
    for (int k = 0; k < 4; k++) {
        const int tk = tid + k * 256;
        float s1 = 0.f, s2 = 0.f, sd = 0.f;
        #pragma unroll
        for (int ep = 0; ep < 3; ep++) {
            const int base = ((b * 3 + ep) * 3) * 1024 + tk;
            s1 += g_part[base];
            s2 += g_part[base + 1024];
            sd += g_part[base + 2048];
        }
        float mu   = s1 * (1.0f / 768.0f);
        float var  = s2 * (1.0f / 768.0f) - mu * mu;
        float rstd = rsqrtf(var + 1e-5f);
        sc[tk] = 0.035355339059327376f * (rstd * (sd - mu * S1) + K2);
    }
    __syncthreads();

    float4 s = *(const float4*)&sc[tid * 4];
    float mx = fmaxf(fmaxf(s.x, s.y), fmaxf(s.z, s.w));
    #pragma unroll
    for (int off = 16; off; off >>= 1)
        mx = fmaxf(mx, __shfl_xor_sync(0xffffffffu, mx, off));
    if ((tid & 31) == 0) red[tid >> 5] = mx;
    __syncthreads();
    float m = red[0];
    #pragma unroll
    for (int i = 1; i < 8; i++) m = fmaxf(m, red[i]);

    float e0 = expf(s.x - m), e1 = expf(s.y - m);
    float e2 = expf(s.z - m), e3 = expf(s.w - m);
    float sum = e0 + e1 + e2 + e3;
    #pragma unroll
    for (int off = 16; off; off >>= 1)
        sum += __shfl_xor_sync(0xffffffffu, sum, off);
    __syncthreads();
    if ((tid & 31) == 0) red[tid >> 5] = sum;
    __syncthreads();
    float tot = 0.f;
    #pragma unroll
    for (int i = 0; i < 8; i++) tot += red[i];
    float inv = 1.0f / tot;

    float4 o = make_float4(e0 * inv, e1 * inv, e2 * inv, e3 * inv);
    *(float4*)&out[b * 1024 + tid * 4] = o;
}

// ============================================================================
extern "C" void kernel_launch(void* const* d_in, const int* in_sizes, int n_in,
                              void* d_out, int out_size)
{
    const float* x      = (const float*)d_in[0];  // (32,1024,32,32)
    const float* gender = (const float*)d_in[1];  // (32,32)
    const float* conv_w = (const float*)d_in[2];  // (768,1024)
    const float* conv_b = (const float*)d_in[3];  // (768)
    const float* ln_g   = (const float*)d_in[4];  // (768)
    const float* ln_b   = (const float*)d_in[5];  // (768)
    const float* cls    = (const float*)d_in[6];  // (1,1,768)
    const float* qkv_w  = (const float*)d_in[7];  // (2400,800)
    const float* qkv_b  = (const float*)d_in[8];  // (2400)

    static int smem_set = 0;
    if (!smem_set) {
        cudaFuncSetAttribute(fused_mma,
                             cudaFuncAttributeMaxDynamicSharedMemorySize,
                             TILES_BYTES);
        smem_set = 1;
    }

    conv_w_kernel<<<768, 256>>>(conv_w);
    conv_x_kernel<<<dim3(32, 16, 32), 256>>>(x);

    prepA1<<<100, 256>>>(cls, qkv_w, qkv_b);
    prepA2<<<dim3(7, 32), 128>>>(qkv_w);
    prepB<<<32, 256>>>(gender, qkv_w, qkv_b, ln_g, ln_b);

    fused_mma<<<152, 512, TILES_BYTES>>>(conv_b, ln_g);

    final_kernel<<<32, 256>>>((float*)d_out);
}

// round 15
// speedup vs baseline: 1.0104x; 1.0104x over previous
#include <cuda_runtime.h>
#include <cuda_bf16.h>
#include <cuda_fp16.h>
#include <math.h>
#include <stdint.h>

// ---------------- scratch (__device__ globals: no allocation allowed) --------
__device__ float g_qc0[800];
__device__ float g_M[33 * 800];
__device__ float g_weff[32 * 800];
__device__ float g_cst[64];
__device__ float g_part[32 * 6 * 3 * 1024];
__device__ int   g_counter;

// fp16 operands: x (hi only, 2^-12 residual dropped), w split hi+lo
__device__ __half g_xh[32 * 1024 * 1024];  // x transposed: [b][m][c]
__device__ __half g_wh[768 * 1024];        // [e][c]
__device__ __half g_wl[768 * 1024];        // w - (float)wh

// ---------------- helpers ----------------------------------------------------
__device__ __forceinline__ uint32_t smem_u32(const void* p) {
    uint32_t a;
    asm("{ .reg .u64 t; cvta.to.shared.u64 t, %1; cvt.u32.u64 %0, t; }"
        : "=r"(a) : "l"(p));
    return a;
}
__device__ __forceinline__ void cp16(uint32_t dst, const void* src) {
    asm volatile("cp.async.cg.shared.global [%0], [%1], 16;"
                 :: "r"(dst), "l"(src) : "memory");
}
#define CP_COMMIT() asm volatile("cp.async.commit_group;" ::: "memory")
#define CP_WAIT(N)  asm volatile("cp.async.wait_group %0;" :: "n"(N) : "memory")

__device__ __forceinline__ void ldsm4(uint32_t* r, uint32_t addr) {
    asm volatile("ldmatrix.sync.aligned.m8n8.x4.shared.b16 {%0,%1,%2,%3}, [%4];"
                 : "=r"(r[0]), "=r"(r[1]), "=r"(r[2]), "=r"(r[3]) : "r"(addr));
}
__device__ __forceinline__ void mma16816h(float* d, const uint32_t* a,
                                          uint32_t b0, uint32_t b1) {
    asm volatile(
        "mma.sync.aligned.m16n8k16.row.col.f32.f16.f16.f32 "
        "{%0,%1,%2,%3}, {%4,%5,%6,%7}, {%8,%9}, {%0,%1,%2,%3};"
        : "+f"(d[0]), "+f"(d[1]), "+f"(d[2]), "+f"(d[3])
        : "r"(a[0]), "r"(a[1]), "r"(a[2]), "r"(a[3]), "r"(b0), "r"(b1));
}

// ============================================================================
// prepA1: qc0[d] = bq[d] + Wq[d,:768].cls + zero g_M + reset counter
// ============================================================================
__global__ void prepA1(const float* __restrict__ cls,
                       const float* __restrict__ qkv_w,
                       const float* __restrict__ qkv_b)
{
    const int tid = threadIdx.x;
    const int gtid = blockIdx.x * 256 + tid;
    for (int f = gtid; f < 33 * 800; f += 100 * 256) g_M[f] = 0.f;
    if (gtid == 0) g_counter = 0;

    const int d = blockIdx.x * 8 + (tid >> 5);
    const int lane = tid & 31;
    const float* wr = qkv_w + (size_t)d * 800;
    float acc = 0.f;
    for (int e = lane; e < 768; e += 32) acc = fmaf(wr[e], cls[e], acc);
    #pragma unroll
    for (int off = 16; off; off >>= 1)
        acc += __shfl_xor_sync(0xffffffffu, acc, off);
    if (lane == 0) g_qc0[d] = acc + qkv_b[d];
}

// ============================================================================
// prepA2: g_M[i][e] += sum_d u[d][i] * Wk[d][e]   (d split into 32 chunks)
// ============================================================================
#define DCH 25
__global__ void prepA2(const float* __restrict__ qkv_w)
{
    __shared__ __align__(16) float us[DCH * 36];
    const int tid = threadIdx.x;
    const int e = blockIdx.x * 128 + tid;
    const int d0 = blockIdx.y * DCH;

    for (int f = tid; f < DCH * 36; f += 128) {
        int dd = f / 36, i = f - dd * 36;
        float v = 0.f;
        if (i == 0)       v = g_qc0[d0 + dd];
        else if (i < 33)  v = qkv_w[(size_t)(d0 + dd) * 800 + 768 + (i - 1)];
        us[f] = v;
    }
    __syncthreads();
    if (e >= 800) return;

    float4 a[9];
    #pragma unroll
    for (int q = 0; q < 9; q++) a[q] = make_float4(0.f, 0.f, 0.f, 0.f);

    const float* wkp = qkv_w + (size_t)(800 + d0) * 800 + e;
    #pragma unroll
    for (int dd = 0; dd < DCH; dd++) {
        float wk = wkp[(size_t)dd * 800];
        const float4* up = (const float4*)&us[dd * 36];
        #pragma unroll
        for (int q = 0; q < 9; q++) {
            float4 u = up[q];
            a[q].x = fmaf(u.x, wk, a[q].x);
            a[q].y = fmaf(u.y, wk, a[q].y);
            a[q].z = fmaf(u.z, wk, a[q].z);
            a[q].w = fmaf(u.w, wk, a[q].w);
        }
    }
    #pragma unroll
    for (int q = 0; q < 9; q++) {
        float c[4] = {a[q].x, a[q].y, a[q].z, a[q].w};
        #pragma unroll
        for (int k = 0; k < 4; k++) {
            int i = q * 4 + k;
            if (i < 33) atomicAdd(&g_M[i * 800 + e], c[k]);
        }
    }
}

// ============================================================================
// prepB: per batch — w_eff = M[0] + g@M[1:], S1, K2
// ============================================================================
__global__ void prepB(const float* __restrict__ gender,
                      const float* __restrict__ qkv_w,
                      const float* __restrict__ qkv_b,
                      const float* __restrict__ ln_g,
                      const float* __restrict__ ln_b)
{
    __shared__ float gs[32];
    __shared__ float red[24];
    const int b = blockIdx.x, tid = threadIdx.x;
    if (tid < 32) gs[tid] = gender[b * 32 + tid];
    __syncthreads();

    float ps1 = 0.f, ps2 = 0.f, pex = 0.f;
    for (int e = tid; e < 800; e += 256) {
        float wf = g_M[e];
        #pragma unroll
        for (int j = 0; j < 32; j++) wf = fmaf(gs[j], g_M[(1 + j) * 800 + e], wf);
        g_weff[b * 800 + e] = wf;
        if (e < 768) { ps1 = fmaf(ln_g[e], wf, ps1); ps2 = fmaf(ln_b[e], wf, ps2); }
        else         { pex = fmaf(gs[e - 768], wf, pex); }
    }
    for (int d = tid; d < 800; d += 256) {
        float qd = g_qc0[d];
        const float* wq = qkv_w + (size_t)d * 800 + 768;
        #pragma unroll
        for (int j = 0; j < 32; j++) qd = fmaf(wq[j], gs[j], qd);
        pex = fmaf(qd, qkv_b[800 + d], pex);
    }
    #pragma unroll
    for (int off = 16; off; off >>= 1) {
        ps1 += __shfl_xor_sync(0xffffffffu, ps1, off);
        ps2 += __shfl_xor_sync(0xffffffffu, ps2, off);
        pex += __shfl_xor_sync(0xffffffffu, pex, off);
    }
    const int w = tid >> 5;
    if ((tid & 31) == 0) { red[w] = ps1; red[8 + w] = ps2; red[16 + w] = pex; }
    __syncthreads();
    if (tid == 0) {
        float S1 = 0.f, S2 = 0.f, EX = 0.f;
        for (int i = 0; i < 8; i++) { S1 += red[i]; S2 += red[8 + i]; EX += red[16 + i]; }
        g_cst[b * 2 + 0] = S1;
        g_cst[b * 2 + 1] = S2 + EX;
    }
}

// ============================================================================
// conv_w: split conv weights into fp16 hi/lo. 768 blocks x 256.
// ============================================================================
__global__ void conv_w_kernel(const float* __restrict__ W)
{
    int i = blockIdx.x * 256 + threadIdx.x;
    #pragma unroll
    for (int k = 0; k < 4; k++) {
        int idx = i + k * 196608;
        float v = W[idx];
        __half h = __float2half(v);
        float r = v - __half2float(h);
        g_wh[idx] = h;
        g_wl[idx] = __float2half(r);
    }
}

// ============================================================================
// conv_x: transpose x[b][c][m] -> x_t[b][m][c] as fp16 (hi only),
// coalesced half2 writes. 64c x 32m tiles.
// ============================================================================
__global__ void conv_x_kernel(const float* __restrict__ x)
{
    __shared__ float s[32][66];
    const int b = blockIdx.z;
    const int m0 = blockIdx.x * 32;
    const int c0 = blockIdx.y * 64;
    const int tid = threadIdx.x;

    const float* xp = x + ((size_t)b * 1024 + c0) * 1024 + m0;
    #pragma unroll
    for (int i = 0; i < 8; i++) {
        int idx = tid + i * 256;
        int cl = idx >> 5, ml = idx & 31;
        s[ml][cl] = xp[(size_t)cl * 1024 + ml];
    }
    __syncthreads();

    const size_t ob = ((size_t)b * 1024 + m0) * 1024 + c0;
    #pragma unroll
    for (int i = 0; i < 4; i++) {
        int idx = tid + i * 256;
        int ml = idx >> 5, pc = idx & 31;
        float2 v = *(const float2*)&s[ml][2 * pc];
        __half2 hp;
        hp.x = __float2half(v.x);
        hp.y = __float2half(v.y);
        *(__half2*)&g_xh[ob + (size_t)ml * 1024 + 2 * pc] = hp;
    }
}

// ============================================================================
// fused_mma: persistent mma.sync fp16 GEMM + LN-stat fold (2-term: hh + hl).
// Task = (b, m-tile 128, e-pass 128). 1536 tasks. 256 threads (4m x 2n warps,
// warp tile 32x64), 2 CTAs/SM. K-chunk 32, cp.async depth-1 single-sync:
//   CP_WAIT(0) -> sync -> issue(kc+1) -> compute(kc).
// Regions per stage (80B padded rows): Ah[128], Bh[128], Bl[128].
// ============================================================================
#define TB 10240                 // 128 rows * 80 bytes
#define BUFSTRIDE (3 * TB)       // 30720
#define TILES_BYTES (2 * 3 * TB) // 61440

__global__ __launch_bounds__(256, 2)
void fused_mma(const float* __restrict__ conv_b, const float* __restrict__ ln_g)
{
    extern __shared__ __align__(16) char tiles[];
    __shared__ float uS[128];
    __shared__ float cbS[128];
    __shared__ float redS[3 * 128];
    __shared__ int s_task;

    const uint32_t ts = smem_u32(tiles);
    const int tid = threadIdx.x;
    const int wid = tid >> 5, lane = tid & 31;
    const int wm = wid & 3, we = wid >> 2;

    const int r0 = tid >> 2, part0 = tid & 3;   // 64 rows x 4 parts

    const uint32_t aoff = (uint32_t)((wm * 32 + (lane & 15)) * 80 + (lane >> 4) * 16);
    const int bg = lane >> 3, br = lane & 7;
    const uint32_t boff = (uint32_t)((we * 64 + ((bg >= 2) ? 8 : 0) + br) * 80 + (bg & 1) * 16);

    while (true) {
        if (tid == 0) s_task = atomicAdd(&g_counter, 1);
        __syncthreads();
        const int task = s_task;
        if (task >= 1536) return;

        const int b  = task / 48;
        const int r_ = task - b * 48;
        const int mt_ = r_ / 6;
        const int ep = r_ - mt_ * 6;
        const int m0 = mt_ * 128;
        const int E0 = ep * 128;

        if (tid < 128) {
            uS[tid]  = ln_g[E0 + tid] * g_weff[b * 800 + E0 + tid];
            cbS[tid] = conv_b[E0 + tid];
        }

        const __half* srcA  = g_xh + (size_t)b * 1048576 + (size_t)m0 * 1024;
        const __half* srcBh = g_wh + (size_t)E0 * 1024;
        const __half* srcBl = g_wl + (size_t)E0 * 1024;

        // one chunk = 6 cp16 per thread (2 rows per region)
        auto issue = [&](int c, int buf) {
            const int c0 = c * 32 + part0 * 8;    // halfs
            const uint32_t dst = ts + (uint32_t)buf * BUFSTRIDE
                               + (uint32_t)(r0 * 80 + part0 * 16);
            cp16(dst,                srcA  + (size_t)r0 * 1024 + c0);
            cp16(dst + 64 * 80,      srcA  + (size_t)(r0 + 64) * 1024 + c0);
            cp16(dst + TB,           srcBh + (size_t)r0 * 1024 + c0);
            cp16(dst + TB + 64 * 80, srcBh + (size_t)(r0 + 64) * 1024 + c0);
            cp16(dst + 2 * TB,           srcBl + (size_t)r0 * 1024 + c0);
            cp16(dst + 2 * TB + 64 * 80, srcBl + (size_t)(r0 + 64) * 1024 + c0);
            CP_COMMIT();
        };

        issue(0, 0);

        float acc[2][8][4];
        #pragma unroll
        for (int i = 0; i < 2; i++)
            #pragma unroll
            for (int j = 0; j < 8; j++)
                #pragma unroll
                for (int k = 0; k < 4; k++) acc[i][j][k] = 0.f;

        for (int kc = 0; kc < 32; kc++) {
            CP_WAIT(0);
            __syncthreads();
            if (kc < 31) issue(kc + 1, (kc + 1) & 1);

            const uint32_t base = ts + (uint32_t)(kc & 1) * BUFSTRIDE;
            const uint32_t tA = base, tBh = base + TB, tBl = base + 2 * TB;

            #pragma unroll
            for (int ks = 0; ks < 2; ks++) {
                const uint32_t ko = ks * 32;
                uint32_t ah[2][4], bb[4][4];
                #pragma unroll
                for (int mt = 0; mt < 2; mt++)
                    ldsm4(ah[mt], tA + aoff + mt * 1280 + ko);
                // B hi: hh
                #pragma unroll
                for (int p = 0; p < 4; p++)
                    ldsm4(bb[p], tBh + boff + p * 1280 + ko);
                #pragma unroll
                for (int mt = 0; mt < 2; mt++)
                    #pragma unroll
                    for (int nt = 0; nt < 8; nt++) {
                        const int p = nt >> 1, o = (nt & 1) * 2;
                        mma16816h(acc[mt][nt], ah[mt], bb[p][o], bb[p][o + 1]);
                    }
                // B lo: hl
                #pragma unroll
                for (int p = 0; p < 4; p++)
                    ldsm4(bb[p], tBl + boff + p * 1280 + ko);
                #pragma unroll
                for (int mt = 0; mt < 2; mt++)
                    #pragma unroll
                    for (int nt = 0; nt < 8; nt++) {
                        const int p = nt >> 1, o = (nt & 1) * 2;
                        mma16816h(acc[mt][nt], ah[mt], bb[p][o], bb[p][o + 1]);
                    }
            }
        }

        // ---- epilogue: fold acc into (s1, s2, sd) ----
        float rs[2][2][3];
        #pragma unroll
        for (int mt = 0; mt < 2; mt++)
            #pragma unroll
            for (int h = 0; h < 2; h++) {
                float s1 = 0.f, s2 = 0.f, sd = 0.f;
                #pragma unroll
                for (int nt = 0; nt < 8; nt++) {
                    #pragma unroll
                    for (int j = 0; j < 2; j++) {
                        const int eL = we * 64 + nt * 8 + (lane & 3) * 2 + j;
                        float p = acc[mt][nt][h * 2 + j] + cbS[eL];
                        s1 += p;
                        s2 = fmaf(p, p, s2);
                        sd = fmaf(p, uS[eL], sd);
                    }
                }
                rs[mt][h][0] = s1; rs[mt][h][1] = s2; rs[mt][h][2] = sd;
            }
        #pragma unroll
        for (int mt = 0; mt < 2; mt++)
            #pragma unroll
            for (int h = 0; h < 2; h++)
                #pragma unroll
                for (int q = 0; q < 3; q++) {
                    rs[mt][h][q] += __shfl_xor_sync(0xffffffffu, rs[mt][h][q], 1);
                    rs[mt][h][q] += __shfl_xor_sync(0xffffffffu, rs[mt][h][q], 2);
                }

        __syncthreads();
        if (we == 1 && (lane & 3) == 0) {
            #pragma unroll
            for (int mt = 0; mt < 2; mt++)
                #pragma unroll
                for (int h = 0; h < 2; h++) {
                    const int m = wm * 32 + mt * 16 + h * 8 + (lane >> 2);
                    redS[0 * 128 + m] = rs[mt][h][0];
                    redS[1 * 128 + m] = rs[mt][h][1];
                    redS[2 * 128 + m] = rs[mt][h][2];
                }
        }
        __syncthreads();
        if (we == 0 && (lane & 3) == 0) {
            const int basep = ((b * 6 + ep) * 3) * 1024 + m0;
            #pragma unroll
            for (int mt = 0; mt < 2; mt++)
                #pragma unroll
                for (int h = 0; h < 2; h++) {
                    const int m = wm * 32 + mt * 16 + h * 8 + (lane >> 2);
                    g_part[basep + m]        = rs[mt][h][0] + redS[0 * 128 + m];
                    g_part[basep + 1024 + m] = rs[mt][h][1] + redS[1 * 128 + m];
                    g_part[basep + 2048 + m] = rs[mt][h][2] + redS[2 * 128 + m];
                }
        }
    }
}

// ============================================================================
// final: combine 6 e-pass partials -> score -> softmax -> out (B,1,32,32)
// ============================================================================
__global__ void final_kernel(float* __restrict__ out)
{
    __shared__ float sc[1024];
    __shared__ float red[8];
    const int b = blockIdx.x, tid = threadIdx.x;
    const float S1 = g_cst[b * 2 + 0];
    const float K2 = g_cst[b * 2 + 1];

    #pragma unroll
    for (int k = 0; k < 4; k++) {
        const int tk = tid + k * 256;
        float s1 = 0.f, s2 = 0.f, sd = 0.f;
        #pragma unroll
        for (int ep = 0; ep < 6; ep++) {
            const int base = ((b * 6 + ep) * 3) * 1024 + tk;
            s1 += g_part[base];
            s2 += g_part[base + 1024];
            sd += g_part[base + 2048];
        }
        float mu   = s1 * (1.0f / 768.0f);
        float var  = s2 * (1.0f / 768.0f) - mu * mu;
        float rstd = rsqrtf(var + 1e-5f);
        sc[tk] = 0.035355339059327376f * (rstd * (sd - mu * S1) + K2);
    }
    __syncthreads();

    float4 s = *(const float4*)&sc[tid * 4];
    float mx = fmaxf(fmaxf(s.x, s.y), fmaxf(s.z, s.w));
    #pragma unroll
    for (int off = 16; off; off >>= 1)
        mx = fmaxf(mx, __shfl_xor_sync(0xffffffffu, mx, off));
    if ((tid & 31) == 0) red[tid >> 5] = mx;
    __syncthreads();
    float m = red[0];
    #pragma unroll
    for (int i = 1; i < 8; i++) m = fmaxf(m, red[i]);

    float e0 = expf(s.x - m), e1 = expf(s.y - m);
    float e2 = expf(s.z - m), e3 = expf(s.w - m);
    float sum = e0 + e1 + e2 + e3;
    #pragma unroll
    for (int off = 16; off; off >>= 1)
        sum += __shfl_xor_sync(0xffffffffu, sum, off);
    __syncthreads();
    if ((tid & 31) == 0) red[tid >> 5] = sum;
    __syncthreads();
    float tot = 0.f;
    #pragma unroll
    for (int i = 0; i < 8; i++) tot += red[i];
    float inv = 1.0f / tot;

    float4 o = make_float4(e0 * inv, e1 * inv, e2 * inv, e3 * inv);
    *(float4*)&out[b * 1024 + tid * 4] = o;
}

// ============================================================================
extern "C" void kernel_launch(void* const* d_in, const int* in_sizes, int n_in,
                              void* d_out, int out_size)
{
    const float* x      = (const float*)d_in[0];  // (32,1024,32,32)
    const float* gender = (const float*)d_in[1];  // (32,32)
    const float* conv_w = (const float*)d_in[2];  // (768,1024)
    const float* conv_b = (const float*)d_in[3];  // (768)
    const float* ln_g   = (const float*)d_in[4];  // (768)
    const float* ln_b   = (const float*)d_in[5];  // (768)
    const float* cls    = (const float*)d_in[6];  // (1,1,768)
    const float* qkv_w  = (const float*)d_in[7];  // (2400,800)
    const float* qkv_b  = (const float*)d_in[8];  // (2400)

    static int smem_set = 0;
    if (!smem_set) {
        cudaFuncSetAttribute(fused_mma,
                             cudaFuncAttributeMaxDynamicSharedMemorySize,
                             TILES_BYTES);
        smem_set = 1;
    }

    conv_w_kernel<<<768, 256>>>(conv_w);
    conv_x_kernel<<<dim3(32, 16, 32), 256>>>(x);

    prepA1<<<100, 256>>>(cls, qkv_w, qkv_b);
    prepA2<<<dim3(7, 32), 128>>>(qkv_w);
    prepB<<<32, 256>>>(gender, qkv_w, qkv_b, ln_g, ln_b);

    fused_mma<<<304, 256, TILES_BYTES>>>(conv_b, ln_g);

    final_kernel<<<32, 256>>>((float*)d_out);
}

// round 16
// speedup vs baseline: 1.4562x; 1.4412x over previous
#include <cuda_runtime.h>
#include <cuda_bf16.h>
#include <cuda_fp16.h>
#include <math.h>
#include <stdint.h>

// ---------------- scratch (__device__ globals: no allocation allowed) --------
__device__ float g_qc0[800];
__device__ float g_M[33 * 800];
__device__ float g_weff[32 * 800];
__device__ float g_cst[64];
__device__ float g_part[32 * 6 * 3 * 1024];
__device__ int   g_counter;

// fp16 operands: x (hi only, 2^-12 residual dropped), w split hi+lo
__device__ __half g_xh[32 * 1024 * 1024];  // x transposed: [b][m][c]
__device__ __half g_wh[768 * 1024];        // [e][c]
__device__ __half g_wl[768 * 1024];        // w - (float)wh

// ---------------- helpers ----------------------------------------------------
__device__ __forceinline__ uint32_t smem_u32(const void* p) {
    uint32_t a;
    asm("{ .reg .u64 t; cvta.to.shared.u64 t, %1; cvt.u32.u64 %0, t; }"
        : "=r"(a) : "l"(p));
    return a;
}
__device__ __forceinline__ void cp16(uint32_t dst, const void* src) {
    asm volatile("cp.async.cg.shared.global [%0], [%1], 16;"
                 :: "r"(dst), "l"(src) : "memory");
}
#define CP_COMMIT() asm volatile("cp.async.commit_group;" ::: "memory")
#define CP_WAIT(N)  asm volatile("cp.async.wait_group %0;" :: "n"(N) : "memory")

__device__ __forceinline__ void ldsm4(uint32_t* r, uint32_t addr) {
    asm volatile("ldmatrix.sync.aligned.m8n8.x4.shared.b16 {%0,%1,%2,%3}, [%4];"
                 : "=r"(r[0]), "=r"(r[1]), "=r"(r[2]), "=r"(r[3]) : "r"(addr));
}
__device__ __forceinline__ void mma16816h(float* d, const uint32_t* a,
                                          uint32_t b0, uint32_t b1) {
    asm volatile(
        "mma.sync.aligned.m16n8k16.row.col.f32.f16.f16.f32 "
        "{%0,%1,%2,%3}, {%4,%5,%6,%7}, {%8,%9}, {%0,%1,%2,%3};"
        : "+f"(d[0]), "+f"(d[1]), "+f"(d[2]), "+f"(d[3])
        : "r"(a[0]), "r"(a[1]), "r"(a[2]), "r"(a[3]), "r"(b0), "r"(b1));
}

// ============================================================================
// prepA1: qc0[d] = bq[d] + Wq[d,:768].cls + zero g_M + reset counter
// ============================================================================
__global__ void prepA1(const float* __restrict__ cls,
                       const float* __restrict__ qkv_w,
                       const float* __restrict__ qkv_b)
{
    const int tid = threadIdx.x;
    const int gtid = blockIdx.x * 256 + tid;
    for (int f = gtid; f < 33 * 800; f += 100 * 256) g_M[f] = 0.f;
    if (gtid == 0) g_counter = 0;

    const int d = blockIdx.x * 8 + (tid >> 5);
    const int lane = tid & 31;
    const float* wr = qkv_w + (size_t)d * 800;
    float acc = 0.f;
    for (int e = lane; e < 768; e += 32) acc = fmaf(wr[e], cls[e], acc);
    #pragma unroll
    for (int off = 16; off; off >>= 1)
        acc += __shfl_xor_sync(0xffffffffu, acc, off);
    if (lane == 0) g_qc0[d] = acc + qkv_b[d];
}

// ============================================================================
// prepA2: g_M[i][e] += sum_d u[d][i] * Wk[d][e]   (d split into 32 chunks)
// ============================================================================
#define DCH 25
__global__ void prepA2(const float* __restrict__ qkv_w)
{
    __shared__ __align__(16) float us[DCH * 36];
    const int tid = threadIdx.x;
    const int e = blockIdx.x * 128 + tid;
    const int d0 = blockIdx.y * DCH;

    for (int f = tid; f < DCH * 36; f += 128) {
        int dd = f / 36, i = f - dd * 36;
        float v = 0.f;
        if (i == 0)       v = g_qc0[d0 + dd];
        else if (i < 33)  v = qkv_w[(size_t)(d0 + dd) * 800 + 768 + (i - 1)];
        us[f] = v;
    }
    __syncthreads();
    if (e >= 800) return;

    float4 a[9];
    #pragma unroll
    for (int q = 0; q < 9; q++) a[q] = make_float4(0.f, 0.f, 0.f, 0.f);

    const float* wkp = qkv_w + (size_t)(800 + d0) * 800 + e;
    #pragma unroll
    for (int dd = 0; dd < DCH; dd++) {
        float wk = wkp[(size_t)dd * 800];
        const float4* up = (const float4*)&us[dd * 36];
        #pragma unroll
        for (int q = 0; q < 9; q++) {
            float4 u = up[q];
            a[q].x = fmaf(u.x, wk, a[q].x);
            a[q].y = fmaf(u.y, wk, a[q].y);
            a[q].z = fmaf(u.z, wk, a[q].z);
            a[q].w = fmaf(u.w, wk, a[q].w);
        }
    }
    #pragma unroll
    for (int q = 0; q < 9; q++) {
        float c[4] = {a[q].x, a[q].y, a[q].z, a[q].w};
        #pragma unroll
        for (int k = 0; k < 4; k++) {
            int i = q * 4 + k;
            if (i < 33) atomicAdd(&g_M[i * 800 + e], c[k]);
        }
    }
}

// ============================================================================
// prepB: per batch — w_eff = M[0] + g@M[1:], S1, K2
// ============================================================================
__global__ void prepB(const float* __restrict__ gender,
                      const float* __restrict__ qkv_w,
                      const float* __restrict__ qkv_b,
                      const float* __restrict__ ln_g,
                      const float* __restrict__ ln_b)
{
    __shared__ float gs[32];
    __shared__ float red[24];
    const int b = blockIdx.x, tid = threadIdx.x;
    if (tid < 32) gs[tid] = gender[b * 32 + tid];
    __syncthreads();

    float ps1 = 0.f, ps2 = 0.f, pex = 0.f;
    for (int e = tid; e < 800; e += 256) {
        float wf = g_M[e];
        #pragma unroll
        for (int j = 0; j < 32; j++) wf = fmaf(gs[j], g_M[(1 + j) * 800 + e], wf);
        g_weff[b * 800 + e] = wf;
        if (e < 768) { ps1 = fmaf(ln_g[e], wf, ps1); ps2 = fmaf(ln_b[e], wf, ps2); }
        else         { pex = fmaf(gs[e - 768], wf, pex); }
    }
    for (int d = tid; d < 800; d += 256) {
        float qd = g_qc0[d];
        const float* wq = qkv_w + (size_t)d * 800 + 768;
        #pragma unroll
        for (int j = 0; j < 32; j++) qd = fmaf(wq[j], gs[j], qd);
        pex = fmaf(qd, qkv_b[800 + d], pex);
    }
    #pragma unroll
    for (int off = 16; off; off >>= 1) {
        ps1 += __shfl_xor_sync(0xffffffffu, ps1, off);
        ps2 += __shfl_xor_sync(0xffffffffu, ps2, off);
        pex += __shfl_xor_sync(0xffffffffu, pex, off);
    }
    const int w = tid >> 5;
    if ((tid & 31) == 0) { red[w] = ps1; red[8 + w] = ps2; red[16 + w] = pex; }
    __syncthreads();
    if (tid == 0) {
        float S1 = 0.f, S2 = 0.f, EX = 0.f;
        for (int i = 0; i < 8; i++) { S1 += red[i]; S2 += red[8 + i]; EX += red[16 + i]; }
        g_cst[b * 2 + 0] = S1;
        g_cst[b * 2 + 1] = S2 + EX;
    }
}

// ============================================================================
// conv_w: split conv weights into fp16 hi/lo. 768 blocks x 256.
// ============================================================================
__global__ void conv_w_kernel(const float* __restrict__ W)
{
    int i = blockIdx.x * 256 + threadIdx.x;
    #pragma unroll
    for (int k = 0; k < 4; k++) {
        int idx = i + k * 196608;
        float v = W[idx];
        __half h = __float2half(v);
        float r = v - __half2float(h);
        g_wh[idx] = h;
        g_wl[idx] = __float2half(r);
    }
}

// ============================================================================
// conv_x: transpose x[b][c][m] -> x_t[b][m][c] as fp16 (hi only),
// coalesced half2 writes. 64c x 32m tiles.
// ============================================================================
__global__ void conv_x_kernel(const float* __restrict__ x)
{
    __shared__ float s[32][66];
    const int b = blockIdx.z;
    const int m0 = blockIdx.x * 32;
    const int c0 = blockIdx.y * 64;
    const int tid = threadIdx.x;

    const float* xp = x + ((size_t)b * 1024 + c0) * 1024 + m0;
    #pragma unroll
    for (int i = 0; i < 8; i++) {
        int idx = tid + i * 256;
        int cl = idx >> 5, ml = idx & 31;
        s[ml][cl] = xp[(size_t)cl * 1024 + ml];
    }
    __syncthreads();

    const size_t ob = ((size_t)b * 1024 + m0) * 1024 + c0;
    #pragma unroll
    for (int i = 0; i < 4; i++) {
        int idx = tid + i * 256;
        int ml = idx >> 5, pc = idx & 31;
        float2 v = *(const float2*)&s[ml][2 * pc];
        __half2 hp;
        hp.x = __float2half(v.x);
        hp.y = __float2half(v.y);
        *(__half2*)&g_xh[ob + (size_t)ml * 1024 + 2 * pc] = hp;
    }
}

// ============================================================================
// fused_mma: persistent mma.sync fp16 GEMM + LN-stat fold (2-term: hh + hl).
// Task = (b, m-tile 128, e-pass 128). 1536 tasks. 256 threads (4m x 2n warps,
// warp tile 32x64), 2 CTAs/SM. K-chunk 32, cp.async 3-STAGE / DEPTH-2:
//   CP_WAIT(1) -> sync -> issue(kc+2) into buf (kc+2)%3 -> compute(kc).
// Chunk kc's data was requested two compute phases earlier -> DRAM latency
// fully hidden (per-chunk latency exposure was the R12-R14 binding constraint).
// Regions per stage (80B padded rows): Ah[128], Bh[128], Bl[128] = 30KB.
// ============================================================================
#define TB 10240                 // 128 rows * 80 bytes
#define BUFSTRIDE (3 * TB)       // 30720
#define TILES_BYTES (3 * 3 * TB) // 92160 (3 stages)

__global__ __launch_bounds__(256, 2)
void fused_mma(const float* __restrict__ conv_b, const float* __restrict__ ln_g)
{
    extern __shared__ __align__(16) char tiles[];
    __shared__ float uS[128];
    __shared__ float cbS[128];
    __shared__ float redS[3 * 128];
    __shared__ int s_task;

    const uint32_t ts = smem_u32(tiles);
    const int tid = threadIdx.x;
    const int wid = tid >> 5, lane = tid & 31;
    const int wm = wid & 3, we = wid >> 2;

    const int r0 = tid >> 2, part0 = tid & 3;   // 64 rows x 4 parts

    const uint32_t aoff = (uint32_t)((wm * 32 + (lane & 15)) * 80 + (lane >> 4) * 16);
    const int bg = lane >> 3, br = lane & 7;
    const uint32_t boff = (uint32_t)((we * 64 + ((bg >= 2) ? 8 : 0) + br) * 80 + (bg & 1) * 16);

    while (true) {
        if (tid == 0) s_task = atomicAdd(&g_counter, 1);
        __syncthreads();
        const int task = s_task;
        if (task >= 1536) return;

        const int b  = task / 48;
        const int r_ = task - b * 48;
        const int mt_ = r_ / 6;
        const int ep = r_ - mt_ * 6;
        const int m0 = mt_ * 128;
        const int E0 = ep * 128;

        if (tid < 128) {
            uS[tid]  = ln_g[E0 + tid] * g_weff[b * 800 + E0 + tid];
            cbS[tid] = conv_b[E0 + tid];
        }

        const __half* srcA  = g_xh + (size_t)b * 1048576 + (size_t)m0 * 1024;
        const __half* srcBh = g_wh + (size_t)E0 * 1024;
        const __half* srcBl = g_wl + (size_t)E0 * 1024;

        // one chunk = 6 cp16 per thread (2 rows per region)
        auto issue = [&](int c, int buf) {
            const int c0 = c * 32 + part0 * 8;    // halfs
            const uint32_t dst = ts + (uint32_t)buf * BUFSTRIDE
                               + (uint32_t)(r0 * 80 + part0 * 16);
            cp16(dst,                srcA  + (size_t)r0 * 1024 + c0);
            cp16(dst + 64 * 80,      srcA  + (size_t)(r0 + 64) * 1024 + c0);
            cp16(dst + TB,           srcBh + (size_t)r0 * 1024 + c0);
            cp16(dst + TB + 64 * 80, srcBh + (size_t)(r0 + 64) * 1024 + c0);
            cp16(dst + 2 * TB,           srcBl + (size_t)r0 * 1024 + c0);
            cp16(dst + 2 * TB + 64 * 80, srcBl + (size_t)(r0 + 64) * 1024 + c0);
            CP_COMMIT();
        };

        issue(0, 0);
        issue(1, 1);

        float acc[2][8][4];
        #pragma unroll
        for (int i = 0; i < 2; i++)
            #pragma unroll
            for (int j = 0; j < 8; j++)
                #pragma unroll
                for (int k = 0; k < 4; k++) acc[i][j][k] = 0.f;

        for (int kc = 0; kc < 32; kc++) {
            // depth-2: chunk kc was issued 2 phases ago; keep 1 group in flight
            if (kc < 31) { CP_WAIT(1); } else { CP_WAIT(0); }
            __syncthreads();
            if (kc < 30) issue(kc + 2, (kc + 2) % 3);

            const uint32_t base = ts + (uint32_t)(kc % 3) * BUFSTRIDE;
            const uint32_t tA = base, tBh = base + TB, tBl = base + 2 * TB;

            #pragma unroll
            for (int ks = 0; ks < 2; ks++) {
                const uint32_t ko = ks * 32;
                uint32_t ah[2][4], bb[4][4];
                #pragma unroll
                for (int mt = 0; mt < 2; mt++)
                    ldsm4(ah[mt], tA + aoff + mt * 1280 + ko);
                // B hi: hh
                #pragma unroll
                for (int p = 0; p < 4; p++)
                    ldsm4(bb[p], tBh + boff + p * 1280 + ko);
                #pragma unroll
                for (int mt = 0; mt < 2; mt++)
                    #pragma unroll
                    for (int nt = 0; nt < 8; nt++) {
                        const int p = nt >> 1, o = (nt & 1) * 2;
                        mma16816h(acc[mt][nt], ah[mt], bb[p][o], bb[p][o + 1]);
                    }
                // B lo: hl
                #pragma unroll
                for (int p = 0; p < 4; p++)
                    ldsm4(bb[p], tBl + boff + p * 1280 + ko);
                #pragma unroll
                for (int mt = 0; mt < 2; mt++)
                    #pragma unroll
                    for (int nt = 0; nt < 8; nt++) {
                        const int p = nt >> 1, o = (nt & 1) * 2;
                        mma16816h(acc[mt][nt], ah[mt], bb[p][o], bb[p][o + 1]);
                    }
            }
        }

        // ---- epilogue: fold acc into (s1, s2, sd) ----
        float rs[2][2][3];
        #pragma unroll
        for (int mt = 0; mt < 2; mt++)
            #pragma unroll
            for (int h = 0; h < 2; h++) {
                float s1 = 0.f, s2 = 0.f, sd = 0.f;
                #pragma unroll
                for (int nt = 0; nt < 8; nt++) {
                    #pragma unroll
                    for (int j = 0; j < 2; j++) {
                        const int eL = we * 64 + nt * 8 + (lane & 3) * 2 + j;
                        float p = acc[mt][nt][h * 2 + j] + cbS[eL];
                        s1 += p;
                        s2 = fmaf(p, p, s2);
                        sd = fmaf(p, uS[eL], sd);
                    }
                }
                rs[mt][h][0] = s1; rs[mt][h][1] = s2; rs[mt][h][2] = sd;
            }
        #pragma unroll
        for (int mt = 0; mt < 2; mt++)
            #pragma unroll
            for (int h = 0; h < 2; h++)
                #pragma unroll
                for (int q = 0; q < 3; q++) {
                    rs[mt][h][q] += __shfl_xor_sync(0xffffffffu, rs[mt][h][q], 1);
                    rs[mt][h][q] += __shfl_xor_sync(0xffffffffu, rs[mt][h][q], 2);
                }

        __syncthreads();
        if (we == 1 && (lane & 3) == 0) {
            #pragma unroll
            for (int mt = 0; mt < 2; mt++)
                #pragma unroll
                for (int h = 0; h < 2; h++) {
                    const int m = wm * 32 + mt * 16 + h * 8 + (lane >> 2);
                    redS[0 * 128 + m] = rs[mt][h][0];
                    redS[1 * 128 + m] = rs[mt][h][1];
                    redS[2 * 128 + m] = rs[mt][h][2];
                }
        }
        __syncthreads();
        if (we == 0 && (lane & 3) == 0) {
            const int basep = ((b * 6 + ep) * 3) * 1024 + m0;
            #pragma unroll
            for (int mt = 0; mt < 2; mt++)
                #pragma unroll
                for (int h = 0; h < 2; h++) {
                    const int m = wm * 32 + mt * 16 + h * 8 + (lane >> 2);
                    g_part[basep + m]        = rs[mt][h][0] + redS[0 * 128 + m];
                    g_part[basep + 1024 + m] = rs[mt][h][1] + redS[1 * 128 + m];
                    g_part[basep + 2048 + m] = rs[mt][h][2] + redS[2 * 128 + m];
                }
        }
    }
}

// ============================================================================
// final: combine 6 e-pass partials -> score -> softmax -> out (B,1,32,32)
// ============================================================================
__global__ void final_kernel(float* __restrict__ out)
{
    __shared__ float sc[1024];
    __shared__ float red[8];
    const int b = blockIdx.x, tid = threadIdx.x;
    const float S1 = g_cst[b * 2 + 0];
    const float K2 = g_cst[b * 2 + 1];

    #pragma unroll
    for (int k = 0; k < 4; k++) {
        const int tk = tid + k * 256;
        float s1 = 0.f, s2 = 0.f, sd = 0.f;
        #pragma unroll
        for (int ep = 0; ep < 6; ep++) {
            const int base = ((b * 6 + ep) * 3) * 1024 + tk;
            s1 += g_part[base];
            s2 += g_part[base + 1024];
            sd += g_part[base + 2048];
        }
        float mu   = s1 * (1.0f / 768.0f);
        float var  = s2 * (1.0f / 768.0f) - mu * mu;
        float rstd = rsqrtf(var + 1e-5f);
        sc[tk] = 0.035355339059327376f * (rstd * (sd - mu * S1) + K2);
    }
    __syncthreads();

    float4 s = *(const float4*)&sc[tid * 4];
    float mx = fmaxf(fmaxf(s.x, s.y), fmaxf(s.z, s.w));
    #pragma unroll
    for (int off = 16; off; off >>= 1)
        mx = fmaxf(mx, __shfl_xor_sync(0xffffffffu, mx, off));
    if ((tid & 31) == 0) red[tid >> 5] = mx;
    __syncthreads();
    float m = red[0];
    #pragma unroll
    for (int i = 1; i < 8; i++) m = fmaxf(m, red[i]);

    float e0 = expf(s.x - m), e1 = expf(s.y - m);
    float e2 = expf(s.z - m), e3 = expf(s.w - m);
    float sum = e0 + e1 + e2 + e3;
    #pragma unroll
    for (int off = 16; off; off >>= 1)
        sum += __shfl_xor_sync(0xffffffffu, sum, off);
    __syncthreads();
    if ((tid & 31) == 0) red[tid >> 5] = sum;
    __syncthreads();
    float tot = 0.f;
    #pragma unroll
    for (int i = 0; i < 8; i++) tot += red[i];
    float inv = 1.0f / tot;

    float4 o = make_float4(e0 * inv, e1 * inv, e2 * inv, e3 * inv);
    *(float4*)&out[b * 1024 + tid * 4] = o;
}

// ============================================================================
extern "C" void kernel_launch(void* const* d_in, const int* in_sizes, int n_in,
                              void* d_out, int out_size)
{
    const float* x      = (const float*)d_in[0];  // (32,1024,32,32)
    const float* gender = (const float*)d_in[1];  // (32,32)
    const float* conv_w = (const float*)d_in[2];  // (768,1024)
    const float* conv_b = (const float*)d_in[3];  // (768)
    const float* ln_g   = (const float*)d_in[4];  // (768)
    const float* ln_b   = (const float*)d_in[5];  // (768)
    const float* cls    = (const float*)d_in[6];  // (1,1,768)
    const float* qkv_w  = (const float*)d_in[7];  // (2400,800)
    const float* qkv_b  = (const float*)d_in[8];  // (2400)

    static int smem_set = 0;
    if (!smem_set) {
        cudaFuncSetAttribute(fused_mma,
                             cudaFuncAttributeMaxDynamicSharedMemorySize,
                             TILES_BYTES);
        smem_set = 1;
    }

    conv_w_kernel<<<768, 256>>>(conv_w);
    conv_x_kernel<<<dim3(32, 16, 32), 256>>>(x);

    prepA1<<<100, 256>>>(cls, qkv_w, qkv_b);
    prepA2<<<dim3(7, 32), 128>>>(qkv_w);
    prepB<<<32, 256>>>(gender, qkv_w, qkv_b, ln_g, ln_b);

    fused_mma<<<304, 256, TILES_BYTES>>>(conv_b, ln_g);

    final_kernel<<<32, 256>>>((float*)d_out);
}

// round 17
// speedup vs baseline: 1.4740x; 1.0122x over previous
#include <cuda_runtime.h>
#include <cuda_bf16.h>
#include <cuda_fp16.h>
#include <math.h>
#include <stdint.h>

// ---------------- scratch (__device__ globals: no allocation allowed) --------
__device__ float g_qc0[800];
__device__ float g_M[33 * 800];
__device__ float g_weff[32 * 800];
__device__ float g_cst[64];
__device__ float g_part[32 * 6 * 3 * 1024];
__device__ int   g_counter;

// fp16 operands (single-term: hi only for both x and w)
__device__ __half g_xh[32 * 1024 * 1024];  // x transposed: [b][m][c]
__device__ __half g_wh[768 * 1024];        // [e][c]

// ---------------- helpers ----------------------------------------------------
__device__ __forceinline__ uint32_t smem_u32(const void* p) {
    uint32_t a;
    asm("{ .reg .u64 t; cvta.to.shared.u64 t, %1; cvt.u32.u64 %0, t; }"
        : "=r"(a) : "l"(p));
    return a;
}
__device__ __forceinline__ void cp16(uint32_t dst, const void* src) {
    asm volatile("cp.async.cg.shared.global [%0], [%1], 16;"
                 :: "r"(dst), "l"(src) : "memory");
}
#define CP_COMMIT() asm volatile("cp.async.commit_group;" ::: "memory")
#define CP_WAIT(N)  asm volatile("cp.async.wait_group %0;" :: "n"(N) : "memory")

__device__ __forceinline__ void ldsm4(uint32_t* r, uint32_t addr) {
    asm volatile("ldmatrix.sync.aligned.m8n8.x4.shared.b16 {%0,%1,%2,%3}, [%4];"
                 : "=r"(r[0]), "=r"(r[1]), "=r"(r[2]), "=r"(r[3]) : "r"(addr));
}
__device__ __forceinline__ void mma16816h(float* d, const uint32_t* a,
                                          uint32_t b0, uint32_t b1) {
    asm volatile(
        "mma.sync.aligned.m16n8k16.row.col.f32.f16.f16.f32 "
        "{%0,%1,%2,%3}, {%4,%5,%6,%7}, {%8,%9}, {%0,%1,%2,%3};"
        : "+f"(d[0]), "+f"(d[1]), "+f"(d[2]), "+f"(d[3])
        : "r"(a[0]), "r"(a[1]), "r"(a[2]), "r"(a[3]), "r"(b0), "r"(b1));
}

// ============================================================================
// prepA1: qc0[d] = bq[d] + Wq[d,:768].cls + zero g_M + reset counter
// ============================================================================
__global__ void prepA1(const float* __restrict__ cls,
                       const float* __restrict__ qkv_w,
                       const float* __restrict__ qkv_b)
{
    const int tid = threadIdx.x;
    const int gtid = blockIdx.x * 256 + tid;
    for (int f = gtid; f < 33 * 800; f += 100 * 256) g_M[f] = 0.f;
    if (gtid == 0) g_counter = 0;

    const int d = blockIdx.x * 8 + (tid >> 5);
    const int lane = tid & 31;
    const float* wr = qkv_w + (size_t)d * 800;
    float acc = 0.f;
    for (int e = lane; e < 768; e += 32) acc = fmaf(wr[e], cls[e], acc);
    #pragma unroll
    for (int off = 16; off; off >>= 1)
        acc += __shfl_xor_sync(0xffffffffu, acc, off);
    if (lane == 0) g_qc0[d] = acc + qkv_b[d];
}

// ============================================================================
// prepA2: g_M[i][e] += sum_d u[d][i] * Wk[d][e]   (d split into 32 chunks)
// ============================================================================
#define DCH 25
__global__ void prepA2(const float* __restrict__ qkv_w)
{
    __shared__ __align__(16) float us[DCH * 36];
    const int tid = threadIdx.x;
    const int e = blockIdx.x * 128 + tid;
    const int d0 = blockIdx.y * DCH;

    for (int f = tid; f < DCH * 36; f += 128) {
        int dd = f / 36, i = f - dd * 36;
        float v = 0.f;
        if (i == 0)       v = g_qc0[d0 + dd];
        else if (i < 33)  v = qkv_w[(size_t)(d0 + dd) * 800 + 768 + (i - 1)];
        us[f] = v;
    }
    __syncthreads();
    if (e >= 800) return;

    float4 a[9];
    #pragma unroll
    for (int q = 0; q < 9; q++) a[q] = make_float4(0.f, 0.f, 0.f, 0.f);

    const float* wkp = qkv_w + (size_t)(800 + d0) * 800 + e;
    #pragma unroll
    for (int dd = 0; dd < DCH; dd++) {
        float wk = wkp[(size_t)dd * 800];
        const float4* up = (const float4*)&us[dd * 36];
        #pragma unroll
        for (int q = 0; q < 9; q++) {
            float4 u = up[q];
            a[q].x = fmaf(u.x, wk, a[q].x);
            a[q].y = fmaf(u.y, wk, a[q].y);
            a[q].z = fmaf(u.z, wk, a[q].z);
            a[q].w = fmaf(u.w, wk, a[q].w);
        }
    }
    #pragma unroll
    for (int q = 0; q < 9; q++) {
        float c[4] = {a[q].x, a[q].y, a[q].z, a[q].w};
        #pragma unroll
        for (int k = 0; k < 4; k++) {
            int i = q * 4 + k;
            if (i < 33) atomicAdd(&g_M[i * 800 + e], c[k]);
        }
    }
}

// ============================================================================
// prepB: per batch — w_eff = M[0] + g@M[1:], S1, K2
// ============================================================================
__global__ void prepB(const float* __restrict__ gender,
                      const float* __restrict__ qkv_w,
                      const float* __restrict__ qkv_b,
                      const float* __restrict__ ln_g,
                      const float* __restrict__ ln_b)
{
    __shared__ float gs[32];
    __shared__ float red[24];
    const int b = blockIdx.x, tid = threadIdx.x;
    if (tid < 32) gs[tid] = gender[b * 32 + tid];
    __syncthreads();

    float ps1 = 0.f, ps2 = 0.f, pex = 0.f;
    for (int e = tid; e < 800; e += 256) {
        float wf = g_M[e];
        #pragma unroll
        for (int j = 0; j < 32; j++) wf = fmaf(gs[j], g_M[(1 + j) * 800 + e], wf);
        g_weff[b * 800 + e] = wf;
        if (e < 768) { ps1 = fmaf(ln_g[e], wf, ps1); ps2 = fmaf(ln_b[e], wf, ps2); }
        else         { pex = fmaf(gs[e - 768], wf, pex); }
    }
    for (int d = tid; d < 800; d += 256) {
        float qd = g_qc0[d];
        const float* wq = qkv_w + (size_t)d * 800 + 768;
        #pragma unroll
        for (int j = 0; j < 32; j++) qd = fmaf(wq[j], gs[j], qd);
        pex = fmaf(qd, qkv_b[800 + d], pex);
    }
    #pragma unroll
    for (int off = 16; off; off >>= 1) {
        ps1 += __shfl_xor_sync(0xffffffffu, ps1, off);
        ps2 += __shfl_xor_sync(0xffffffffu, ps2, off);
        pex += __shfl_xor_sync(0xffffffffu, pex, off);
    }
    const int w = tid >> 5;
    if ((tid & 31) == 0) { red[w] = ps1; red[8 + w] = ps2; red[16 + w] = pex; }
    __syncthreads();
    if (tid == 0) {
        float S1 = 0.f, S2 = 0.f, EX = 0.f;
        for (int i = 0; i < 8; i++) { S1 += red[i]; S2 += red[8 + i]; EX += red[16 + i]; }
        g_cst[b * 2 + 0] = S1;
        g_cst[b * 2 + 1] = S2 + EX;
    }
}

// ============================================================================
// conv_w: convert conv weights to fp16. 768 blocks x 256.
// ============================================================================
__global__ void conv_w_kernel(const float* __restrict__ W)
{
    int i = blockIdx.x * 256 + threadIdx.x;
    #pragma unroll
    for (int k = 0; k < 4; k++) {
        int idx = i + k * 196608;
        g_wh[idx] = __float2half(W[idx]);
    }
}

// ============================================================================
// conv_x: transpose x[b][c][m] -> x_t[b][m][c] as fp16,
// coalesced half2 writes. 64c x 32m tiles.
// ============================================================================
__global__ void conv_x_kernel(const float* __restrict__ x)
{
    __shared__ float s[32][66];
    const int b = blockIdx.z;
    const int m0 = blockIdx.x * 32;
    const int c0 = blockIdx.y * 64;
    const int tid = threadIdx.x;

    const float* xp = x + ((size_t)b * 1024 + c0) * 1024 + m0;
    #pragma unroll
    for (int i = 0; i < 8; i++) {
        int idx = tid + i * 256;
        int cl = idx >> 5, ml = idx & 31;
        s[ml][cl] = xp[(size_t)cl * 1024 + ml];
    }
    __syncthreads();

    const size_t ob = ((size_t)b * 1024 + m0) * 1024 + c0;
    #pragma unroll
    for (int i = 0; i < 4; i++) {
        int idx = tid + i * 256;
        int ml = idx >> 5, pc = idx & 31;
        float2 v = *(const float2*)&s[ml][2 * pc];
        __half2 hp;
        hp.x = __float2half(v.x);
        hp.y = __float2half(v.y);
        *(__half2*)&g_xh[ob + (size_t)ml * 1024 + 2 * pc] = hp;
    }
}

// ============================================================================
// fused_mma: persistent mma.sync fp16 GEMM + LN-stat fold (SINGLE term).
// Task = (b, m-tile 128, e-pass 128). 1536 tasks. 256 threads (4m x 2n warps,
// warp tile 32x64), 2 CTAs/SM. K-chunk 32, cp.async 3-STAGE / DEPTH-2:
//   CP_WAIT(1) -> sync -> issue(kc+2) into buf (kc+2)%3 -> compute(kc).
// Regions per stage (80B padded rows): A[128], B[128] = 20KB.
// ============================================================================
#define TB 10240                 // 128 rows * 80 bytes
#define BUFSTRIDE (2 * TB)       // 20480
#define TILES_BYTES (3 * 2 * TB) // 61440 (3 stages)

__global__ __launch_bounds__(256, 2)
void fused_mma(const float* __restrict__ conv_b, const float* __restrict__ ln_g)
{
    extern __shared__ __align__(16) char tiles[];
    __shared__ float uS[128];
    __shared__ float cbS[128];
    __shared__ float redS[3 * 128];
    __shared__ int s_task;

    const uint32_t ts = smem_u32(tiles);
    const int tid = threadIdx.x;
    const int wid = tid >> 5, lane = tid & 31;
    const int wm = wid & 3, we = wid >> 2;

    const int r0 = tid >> 2, part0 = tid & 3;   // 64 rows x 4 parts

    const uint32_t aoff = (uint32_t)((wm * 32 + (lane & 15)) * 80 + (lane >> 4) * 16);
    const int bg = lane >> 3, br = lane & 7;
    const uint32_t boff = (uint32_t)((we * 64 + ((bg >= 2) ? 8 : 0) + br) * 80 + (bg & 1) * 16);

    while (true) {
        if (tid == 0) s_task = atomicAdd(&g_counter, 1);
        __syncthreads();
        const int task = s_task;
        if (task >= 1536) return;

        const int b  = task / 48;
        const int r_ = task - b * 48;
        const int mt_ = r_ / 6;
        const int ep = r_ - mt_ * 6;
        const int m0 = mt_ * 128;
        const int E0 = ep * 128;

        if (tid < 128) {
            uS[tid]  = ln_g[E0 + tid] * g_weff[b * 800 + E0 + tid];
            cbS[tid] = conv_b[E0 + tid];
        }

        const __half* srcA = g_xh + (size_t)b * 1048576 + (size_t)m0 * 1024;
        const __half* srcB = g_wh + (size_t)E0 * 1024;

        // one chunk = 4 cp16 per thread (2 rows per region)
        auto issue = [&](int c, int buf) {
            const int c0 = c * 32 + part0 * 8;    // halfs
            const uint32_t dst = ts + (uint32_t)buf * BUFSTRIDE
                               + (uint32_t)(r0 * 80 + part0 * 16);
            cp16(dst,                srcA + (size_t)r0 * 1024 + c0);
            cp16(dst + 64 * 80,      srcA + (size_t)(r0 + 64) * 1024 + c0);
            cp16(dst + TB,           srcB + (size_t)r0 * 1024 + c0);
            cp16(dst + TB + 64 * 80, srcB + (size_t)(r0 + 64) * 1024 + c0);
            CP_COMMIT();
        };

        issue(0, 0);
        issue(1, 1);

        float acc[2][8][4];
        #pragma unroll
        for (int i = 0; i < 2; i++)
            #pragma unroll
            for (int j = 0; j < 8; j++)
                #pragma unroll
                for (int k = 0; k < 4; k++) acc[i][j][k] = 0.f;

        for (int kc = 0; kc < 32; kc++) {
            // depth-2: chunk kc was issued 2 phases ago; keep 1 group in flight
            if (kc < 31) { CP_WAIT(1); } else { CP_WAIT(0); }
            __syncthreads();
            if (kc < 30) issue(kc + 2, (kc + 2) % 3);

            const uint32_t base = ts + (uint32_t)(kc % 3) * BUFSTRIDE;
            const uint32_t tA = base, tB = base + TB;

            #pragma unroll
            for (int ks = 0; ks < 2; ks++) {
                const uint32_t ko = ks * 32;
                uint32_t ah[2][4], bb[4][4];
                #pragma unroll
                for (int mt = 0; mt < 2; mt++)
                    ldsm4(ah[mt], tA + aoff + mt * 1280 + ko);
                #pragma unroll
                for (int p = 0; p < 4; p++)
                    ldsm4(bb[p], tB + boff + p * 1280 + ko);
                #pragma unroll
                for (int mt = 0; mt < 2; mt++)
                    #pragma unroll
                    for (int nt = 0; nt < 8; nt++) {
                        const int p = nt >> 1, o = (nt & 1) * 2;
                        mma16816h(acc[mt][nt], ah[mt], bb[p][o], bb[p][o + 1]);
                    }
            }
        }

        // ---- epilogue: fold acc into (s1, s2, sd) ----
        float rs[2][2][3];
        #pragma unroll
        for (int mt = 0; mt < 2; mt++)
            #pragma unroll
            for (int h = 0; h < 2; h++) {
                float s1 = 0.f, s2 = 0.f, sd = 0.f;
                #pragma unroll
                for (int nt = 0; nt < 8; nt++) {
                    #pragma unroll
                    for (int j = 0; j < 2; j++) {
                        const int eL = we * 64 + nt * 8 + (lane & 3) * 2 + j;
                        float p = acc[mt][nt][h * 2 + j] + cbS[eL];
                        s1 += p;
                        s2 = fmaf(p, p, s2);
                        sd = fmaf(p, uS[eL], sd);
                    }
                }
                rs[mt][h][0] = s1; rs[mt][h][1] = s2; rs[mt][h][2] = sd;
            }
        #pragma unroll
        for (int mt = 0; mt < 2; mt++)
            #pragma unroll
            for (int h = 0; h < 2; h++)
                #pragma unroll
                for (int q = 0; q < 3; q++) {
                    rs[mt][h][q] += __shfl_xor_sync(0xffffffffu, rs[mt][h][q], 1);
                    rs[mt][h][q] += __shfl_xor_sync(0xffffffffu, rs[mt][h][q], 2);
                }

        __syncthreads();
        if (we == 1 && (lane & 3) == 0) {
            #pragma unroll
            for (int mt = 0; mt < 2; mt++)
                #pragma unroll
                for (int h = 0; h < 2; h++) {
                    const int m = wm * 32 + mt * 16 + h * 8 + (lane >> 2);
                    redS[0 * 128 + m] = rs[mt][h][0];
                    redS[1 * 128 + m] = rs[mt][h][1];
                    redS[2 * 128 + m] = rs[mt][h][2];
                }
        }
        __syncthreads();
        if (we == 0 && (lane & 3) == 0) {
            const int basep = ((b * 6 + ep) * 3) * 1024 + m0;
            #pragma unroll
            for (int mt = 0; mt < 2; mt++)
                #pragma unroll
                for (int h = 0; h < 2; h++) {
                    const int m = wm * 32 + mt * 16 + h * 8 + (lane >> 2);
                    g_part[basep + m]        = rs[mt][h][0] + redS[0 * 128 + m];
                    g_part[basep + 1024 + m] = rs[mt][h][1] + redS[1 * 128 + m];
                    g_part[basep + 2048 + m] = rs[mt][h][2] + redS[2 * 128 + m];
                }
        }
    }
}

// ============================================================================
// final: combine 6 e-pass partials -> score -> softmax -> out (B,1,32,32)
// ============================================================================
__global__ void final_kernel(float* __restrict__ out)
{
    __shared__ float sc[1024];
    __shared__ float red[8];
    const int b = blockIdx.x, tid = threadIdx.x;
    const float S1 = g_cst[b * 2 + 0];
    const float K2 = g_cst[b * 2 + 1];

    #pragma unroll
    for (int k = 0; k < 4; k++) {
        const int tk = tid + k * 256;
        float s1 = 0.f, s2 = 0.f, sd = 0.f;
        #pragma unroll
        for (int ep = 0; ep < 6; ep++) {
            const int base = ((b * 6 + ep) * 3) * 1024 + tk;
            s1 += g_part[base];
            s2 += g_part[base + 1024];
            sd += g_part[base + 2048];
        }
        float mu   = s1 * (1.0f / 768.0f);
        float var  = s2 * (1.0f / 768.0f) - mu * mu;
        float rstd = rsqrtf(var + 1e-5f);
        sc[tk] = 0.035355339059327376f * (rstd * (sd - mu * S1) + K2);
    }
    __syncthreads();

    float4 s = *(const float4*)&sc[tid * 4];
    float mx = fmaxf(fmaxf(s.x, s.y), fmaxf(s.z, s.w));
    #pragma unroll
    for (int off = 16; off; off >>= 1)
        mx = fmaxf(mx, __shfl_xor_sync(0xffffffffu, mx, off));
    if ((tid & 31) == 0) red[tid >> 5] = mx;
    __syncthreads();
    float m = red[0];
    #pragma unroll
    for (int i = 1; i < 8; i++) m = fmaxf(m, red[i]);

    float e0 = expf(s.x - m), e1 = expf(s.y - m);
    float e2 = expf(s.z - m), e3 = expf(s.w - m);
    float sum = e0 + e1 + e2 + e3;
    #pragma unroll
    for (int off = 16; off; off >>= 1)
        sum += __shfl_xor_sync(0xffffffffu, sum, off);
    __syncthreads();
    if ((tid & 31) == 0) red[tid >> 5] = sum;
    __syncthreads();
    float tot = 0.f;
    #pragma unroll
    for (int i = 0; i < 8; i++) tot += red[i];
    float inv = 1.0f / tot;

    float4 o = make_float4(e0 * inv, e1 * inv, e2 * inv, e3 * inv);
    *(float4*)&out[b * 1024 + tid * 4] = o;
}

// ============================================================================
extern "C" void kernel_launch(void* const* d_in, const int* in_sizes, int n_in,
                              void* d_out, int out_size)
{
    const float* x      = (const float*)d_in[0];  // (32,1024,32,32)
    const float* gender = (const float*)d_in[1];  // (32,32)
    const float* conv_w = (const float*)d_in[2];  // (768,1024)
    const float* conv_b = (const float*)d_in[3];  // (768)
    const float* ln_g   = (const float*)d_in[4];  // (768)
    const float* ln_b   = (const float*)d_in[5];  // (768)
    const float* cls    = (const float*)d_in[6];  // (1,1,768)
    const float* qkv_w  = (const float*)d_in[7];  // (2400,800)
    const float* qkv_b  = (const float*)d_in[8];  // (2400)

    static int smem_set = 0;
    if (!smem_set) {
        cudaFuncSetAttribute(fused_mma,
                             cudaFuncAttributeMaxDynamicSharedMemorySize,
                             TILES_BYTES);
        smem_set = 1;
    }

    conv_w_kernel<<<768, 256>>>(conv_w);
    conv_x_kernel<<<dim3(32, 16, 32), 256>>>(x);

    prepA1<<<100, 256>>>(cls, qkv_w, qkv_b);
    prepA2<<<dim3(7, 32), 128>>>(qkv_w);
    prepB<<<32, 256>>>(gender, qkv_w, qkv_b, ln_g, ln_b);

    fused_mma<<<304, 256, TILES_BYTES>>>(conv_b, ln_g);

    final_kernel<<<32, 256>>>((float*)d_out);
}